// round 1
// baseline (speedup 1.0000x reference)
#include <cuda_runtime.h>
#include <math.h>

#define NB 64
#define NT 512
#define NE 256
#define NH 512

// ---------------- device scratch (static, no runtime allocation) ----------------
__device__ float g_xe[2][NT][NB][NH];          // precomputed input projections, [branch][t][b][h]  (128 MB)
__device__ float g_h[2][2][NB * NH];           // double-buffered hidden state per branch
__device__ volatile unsigned g_flags[2][64];   // per-branch, per-CTA step flags
__device__ unsigned g_count[2];                // self-resetting barrier state
__device__ unsigned g_gen[2];

// ---------------- out init: out[b] = fc_b ----------------
__global__ void init_out_kernel(float* out, const float* __restrict__ fcb) {
    if (threadIdx.x < NB) out[threadIdx.x] = fcb[0];
}

// ---------------- projection: xe[br][t][b][:] = emb_table[x[b,t]] @ Wx + bias ----------------
// Tiled fp32 GEMM with embedding gather on A. Tile 64(m=t within fixed b) x 64(n), K staged 64 at a time.
__global__ __launch_bounds__(256) void proj_kernel(
    const int* __restrict__ x, const float* __restrict__ emb,
    const float* __restrict__ Wx0, const float* __restrict__ b0,
    const float* __restrict__ Wx1, const float* __restrict__ b1)
{
    __shared__ float A_s[64][68];   // [m][k], padded row (272B, 16B aligned)
    __shared__ float B_s[64][64];   // [k][n]
    __shared__ int   xrow[64];

    const int tid = threadIdx.x;
    const int n0  = blockIdx.x * 64;
    const int my  = blockIdx.y;          // m-tile: 64 consecutive t of one batch row
    const int br  = blockIdx.z;
    const int b   = my >> 3;
    const int t0  = (my & 7) << 6;

    const float* Wx   = br ? Wx1 : Wx0;
    const float* bias = br ? b1  : b0;

    if (tid < 64) xrow[tid] = x[b * NT + t0 + tid];
    __syncthreads();

    const int ni = tid & 15;   // n sub-tile (4 cols)
    const int mg = tid >> 4;   // m sub-tile (4 rows)

    float acc[4][4];
#pragma unroll
    for (int i = 0; i < 4; i++)
#pragma unroll
        for (int j = 0; j < 4; j++) acc[i][j] = 0.f;

    for (int kt = 0; kt < 4; kt++) {
        // stage A (gathered embedding rows), 64x64 floats
        for (int l = tid; l < 1024; l += 256) {
            int r = l >> 4, jj = l & 15;
            float4 v = *(const float4*)(emb + (size_t)xrow[r] * NE + kt * 64 + jj * 4);
            *(float4*)&A_s[r][jj * 4] = v;
        }
        // stage B (Wx tile), 64x64 floats
        for (int l = tid; l < 1024; l += 256) {
            int kk = l >> 4, jj = l & 15;
            *(float4*)&B_s[kk][jj * 4] =
                *(const float4*)(Wx + (size_t)(kt * 64 + kk) * NH + n0 + jj * 4);
        }
        __syncthreads();

#pragma unroll 8
        for (int kk = 0; kk < 64; kk++) {
            float4 bv = *(const float4*)&B_s[kk][ni * 4];
#pragma unroll
            for (int i = 0; i < 4; i++) {
                float a = A_s[mg * 4 + i][kk];
                acc[i][0] += a * bv.x;
                acc[i][1] += a * bv.y;
                acc[i][2] += a * bv.z;
                acc[i][3] += a * bv.w;
            }
        }
        __syncthreads();
    }

    float4 bb = *(const float4*)(bias + n0 + ni * 4);
#pragma unroll
    for (int i = 0; i < 4; i++) {
        int t = t0 + mg * 4 + i;
        float4 o;
        o.x = acc[i][0] + bb.x; o.y = acc[i][1] + bb.y;
        o.z = acc[i][2] + bb.z; o.w = acc[i][3] + bb.w;
        *(float4*)&g_xe[br][t][b][n0 + ni * 4] = o;
    }
}

// ---------------- self-resetting per-branch barrier (64 CTAs) ----------------
__device__ __forceinline__ void branch_barrier(int br) {
    __syncthreads();
    if (threadIdx.x == 0) {
        __threadfence();
        unsigned g  = *(volatile unsigned*)&g_gen[br];
        unsigned my = atomicAdd(&g_count[br], 1u);
        if (my == 63u) {
            g_count[br] = 0u;            // self-reset => deterministic across graph replays
            __threadfence();
            atomicAdd(&g_gen[br], 1u);
        } else {
            while (*(volatile unsigned*)&g_gen[br] == g) {}
        }
        __threadfence();
    }
    __syncthreads();
}

// ---------------- persistent recurrence ----------------
// 128 CTAs (64 per branch) x 128 threads. CTA owns 8 columns of Wh (16KB SMEM, [k4][c][4] layout).
// Each step: h_new[:, cols] = act(xe_t[:, cols] + h @ Wh[:, cols]); h exchanged via L2 (.cg ops).
__global__ __launch_bounds__(128) void rec_kernel(
    const float* __restrict__ Wh0, const float* __restrict__ Wh1,
    const float* __restrict__ fcw, float* out)
{
    __shared__ float Wh_s[4096];   // 512 k x 8 cols, interleaved [k4][c][4] for conflict-free LDS.128
    __shared__ float red[64];

    const int tid = threadIdx.x;
    const int br  = blockIdx.x >> 6;
    const int cid = blockIdx.x & 63;
    const int c0  = cid << 3;
    const float* Wh = br ? Wh1 : Wh0;

    // load Wh slice once (persists all 512 steps)
    for (int l = tid; l < 4096; l += 128) {
        int k = l >> 3, cc = l & 7;
        Wh_s[(k >> 2) * 32 + cc * 4 + (k & 3)] = Wh[k * NH + c0 + cc];
    }
    // zero h parity-0 slice (re-done every launch => replay-deterministic)
    {
        float* h0p = g_h[br][0];
        for (int l = tid; l < 512; l += 128) {
            int bb = l >> 3, cc = l & 7;
            h0p[bb * NH + c0 + cc] = 0.f;
        }
    }
    if (tid == 0) g_flags[br][cid] = 0u;
    branch_barrier(br);

    const int c   = tid & 7;    // column within slice
    const int bq  = tid >> 3;   // 0..15 ; thread handles b = bq + 16*j, j=0..3
    const int col = c0 + c;
    const float wfc = fcw[br * NH + col];
    float v[4] = {0.f, 0.f, 0.f, 0.f};

    const float4* w4 = (const float4*)Wh_s;  // [k4*8 + c]

    for (int t = 0; t < NT; t++) {
        const float* hr = g_h[br][t & 1];
        float*       hw = g_h[br][(~t) & 1];

        float acc[4];
#pragma unroll
        for (int j = 0; j < 4; j++)
            acc[j] = g_xe[br][t][bq + 16 * j][col];

#pragma unroll 4
        for (int k4 = 0; k4 < 128; k4++) {
            float4 w = w4[k4 * 8 + c];
#pragma unroll
            for (int j = 0; j < 4; j++) {
                float4 h = __ldcg((const float4*)(hr + (bq + 16 * j) * NH + k4 * 4));
                acc[j] += h.x * w.x + h.y * w.y + h.z * w.z + h.w * w.w;
            }
        }

#pragma unroll
        for (int j = 0; j < 4; j++) {
            float r_ = br ? fmaxf(acc[j], 0.f) : tanhf(acc[j]);
            v[j] = r_;
            __stcg(hw + (bq + 16 * j) * NH + col, r_);
        }

        __threadfence();               // publish h writes (L2)
        __syncthreads();
        if (tid == 0) g_flags[br][cid] = (unsigned)(t + 1);
        if (tid < 64) { while (g_flags[br][tid] < (unsigned)(t + 1)) {} }
        __syncthreads();
        __threadfence();               // acquire before next step's h reads
    }

    // final: out[b] += sum over owned cols of h_T[b,col] * fc_w[br*H + col]
    if (tid < 64) red[tid] = 0.f;
    __syncthreads();
#pragma unroll
    for (int j = 0; j < 4; j++)
        atomicAdd(&red[bq + 16 * j], v[j] * wfc);
    __syncthreads();
    if (tid < 64) atomicAdd(&out[tid], red[tid]);
}

// ---------------- launch ----------------
extern "C" void kernel_launch(void* const* d_in, const int* in_sizes, int n_in,
                              void* d_out, int out_size) {
    const int*   x    = (const int*)  d_in[0];
    const float* emb  = (const float*)d_in[1];
    const float* Wx0  = (const float*)d_in[2];
    const float* Wh0  = (const float*)d_in[3];
    const float* b0   = (const float*)d_in[4];
    const float* Wx1  = (const float*)d_in[5];
    const float* Wh1  = (const float*)d_in[6];
    const float* b1   = (const float*)d_in[7];
    const float* fcw  = (const float*)d_in[8];
    const float* fcb  = (const float*)d_in[9];
    float* out = (float*)d_out;

    init_out_kernel<<<1, 64>>>(out, fcb);
    proj_kernel<<<dim3(8, 512, 2), 256>>>(x, emb, Wx0, b0, Wx1, b1);
    rec_kernel<<<128, 128>>>(Wh0, Wh1, fcw, out);
}

// round 3
// speedup vs baseline: 3.8082x; 3.8082x over previous
#include <cuda_runtime.h>
#include <math.h>

#define NB 64
#define NT 512
#define NE 256
#define NH 512

typedef unsigned long long u64;

// ---------------- device scratch (static, no runtime allocation) ----------------
__device__ __align__(256) float g_xe[2][NT][NB][NH];   // input projections [branch][t][b][h] (128 MB)
__device__ __align__(256) float g_h[2][2][NB][NH];     // double-buffered hidden state per branch

// ---------------- small helpers ----------------
__device__ __forceinline__ u64 dup2(float x) {
    u64 r; asm("mov.b64 %0, {%1, %1};" : "=l"(r) : "f"(x)); return r;
}
__device__ __forceinline__ u64 pack2(float lo, float hi) {
    u64 r; asm("mov.b64 %0, {%1, %2};" : "=l"(r) : "f"(lo), "f"(hi)); return r;
}
__device__ __forceinline__ void unpack2(u64 v, float& lo, float& hi) {
    asm("mov.b64 {%0, %1}, %2;" : "=f"(lo), "=f"(hi) : "l"(v));
}
__device__ __forceinline__ void fma2(u64& d, u64 a, u64 b) {
    asm("fma.rn.f32x2 %0, %1, %2, %3;" : "=l"(d) : "l"(a), "l"(b), "l"(d));
}
__device__ __forceinline__ float tanh_fast(float x) {
    float y; asm("tanh.approx.f32 %0, %1;" : "=f"(y) : "f"(x)); return y;
}
__device__ __forceinline__ void cp16cg(void* smem_dst, const void* gsrc) {
    unsigned sd = (unsigned)__cvta_generic_to_shared(smem_dst);
    asm volatile("cp.async.cg.shared.global [%0], [%1], 16;" :: "r"(sd), "l"(gsrc));
}
#define CP_COMMIT() asm volatile("cp.async.commit_group;" ::: "memory")
#define CP_WAIT1()  asm volatile("cp.async.wait_group 1;" ::: "memory")
#define CLUSTER_BAR() do { \
    asm volatile("barrier.cluster.arrive.aligned;" ::: "memory"); \
    asm volatile("barrier.cluster.wait.aligned;"   ::: "memory"); \
} while (0)

// ---------------- out init: out[b] = fc_b ----------------
__global__ void init_out_kernel(float* out, const float* __restrict__ fcb) {
    if (threadIdx.x < NB) out[threadIdx.x] = fcb[0];
}

// ---------------- projection: xe[br][t][b][:] = emb_table[x[b,t]] @ Wx + bias ----------------
__global__ __launch_bounds__(256) void proj_kernel(
    const int* __restrict__ x, const float* __restrict__ emb,
    const float* __restrict__ Wx0, const float* __restrict__ b0,
    const float* __restrict__ Wx1, const float* __restrict__ b1)
{
    __shared__ float A_s[64][68];
    __shared__ float B_s[64][64];
    __shared__ int   xrow[64];

    const int tid = threadIdx.x;
    const int n0  = blockIdx.x * 64;
    const int my  = blockIdx.y;
    const int br  = blockIdx.z;
    const int b   = my >> 3;
    const int t0  = (my & 7) << 6;

    const float* Wx   = br ? Wx1 : Wx0;
    const float* bias = br ? b1  : b0;

    if (tid < 64) xrow[tid] = x[b * NT + t0 + tid];
    __syncthreads();

    const int ni = tid & 15;
    const int mg = tid >> 4;

    float acc[4][4];
#pragma unroll
    for (int i = 0; i < 4; i++)
#pragma unroll
        for (int j = 0; j < 4; j++) acc[i][j] = 0.f;

    for (int kt = 0; kt < 4; kt++) {
        for (int l = tid; l < 1024; l += 256) {
            int r = l >> 4, jj = l & 15;
            float4 v = *(const float4*)(emb + (size_t)xrow[r] * NE + kt * 64 + jj * 4);
            *(float4*)&A_s[r][jj * 4] = v;
        }
        for (int l = tid; l < 1024; l += 256) {
            int kk = l >> 4, jj = l & 15;
            *(float4*)&B_s[kk][jj * 4] =
                *(const float4*)(Wx + (size_t)(kt * 64 + kk) * NH + n0 + jj * 4);
        }
        __syncthreads();

#pragma unroll 8
        for (int kk = 0; kk < 64; kk++) {
            float4 bv = *(const float4*)&B_s[kk][ni * 4];
#pragma unroll
            for (int i = 0; i < 4; i++) {
                float a = A_s[mg * 4 + i][kk];
                acc[i][0] += a * bv.x;
                acc[i][1] += a * bv.y;
                acc[i][2] += a * bv.z;
                acc[i][3] += a * bv.w;
            }
        }
        __syncthreads();
    }

    float4 bb = *(const float4*)(bias + n0 + ni * 4);
#pragma unroll
    for (int i = 0; i < 4; i++) {
        int t = t0 + mg * 4 + i;
        float4 o;
        o.x = acc[i][0] + bb.x; o.y = acc[i][1] + bb.y;
        o.z = acc[i][2] + bb.z; o.w = acc[i][3] + bb.w;
        *(float4*)&g_xe[br][t][b][n0 + ni * 4] = o;
    }
}

// ---------------- persistent recurrence ----------------
// 128 CTAs x 128 threads, clusters of 8. Per branch: 8 batch-groups (8 b each) x 8
// col-groups (64 cols each). Cluster = the 8 CTAs sharing one batch-group (the only
// sync domain, since batch rows are independent recurrences).
// CTA keeps Wh[:, 64 cols] (128 KB) in SMEM for all 512 steps; per step it cp.async's
// its 8 h-rows (16 KB) from the L2-resident double buffer, computes
// h_new[8b x 64c] with packed f32x2 FMAs, writes back via stcg, cluster-barriers.
extern __shared__ float rec_smem[];
__global__ __launch_bounds__(128, 1) __cluster_dims__(8, 1, 1)
void rec_kernel(const float* __restrict__ Wh0, const float* __restrict__ Wh1,
                const float* __restrict__ fcw, float* out)
{
    float* Wh_s = rec_smem;                    // [512][64]   128 KB
    float* h_s  = rec_smem + NH * 64;          // [8][512]     16 KB
    float* xe_s = rec_smem + NH * 64 + 8 * NH; // [2][8][64]    4 KB

    const int tid = threadIdx.x;
    const int bx  = blockIdx.x;
    const int br  = bx >> 6;
    const int id  = bx & 63;
    const int bg  = id >> 3;
    const int cg  = id & 7;
    const int c0  = cg * 64;
    const float* Wh = br ? Wh1 : Wh0;

    // persistent Wh slice load: [k][0..63] <- Wh[k][c0..c0+63]
    for (int l = tid; l < NH * 16; l += 128) {
        int k = l >> 4, q = l & 15;
        *(float4*)&Wh_s[k * 64 + q * 4] = *(const float4*)&Wh[k * NH + c0 + q * 4];
    }

    const int bl  = tid >> 4;        // 0..7  local batch row
    const int b   = bg * 8 + bl;     // global batch row
    const int cq  = tid & 15;        // col quad within slice
    const int col = c0 + cq * 4;

    // zero h parity-0 slice (re-done every launch => replay-deterministic)
    {
        float4 z = make_float4(0.f, 0.f, 0.f, 0.f);
        __stcg((float4*)&g_h[br][0][b][col], z);
    }
    // prefetch xe for t=0
    cp16cg(&xe_s[bl * 64 + cq * 4], &g_xe[br][0][b][col]);
    CP_COMMIT();

    __syncthreads();       // Wh_s ready within CTA
    CLUSTER_BAR();         // zeroed h buf0 visible across the row

    float v0 = 0.f, v1 = 0.f, v2 = 0.f, v3 = 0.f;
    const ulonglong2* wrow = (const ulonglong2*)Wh_s;   // [k][16] pairs; idx k*16+cq

    for (int t = 0; t < NT; t++) {
        // stage h(t) row block (16 KB, coalesced, L2-only)
        const char* hsrc = (const char*)&g_h[br][t & 1][bg * 8][0];
        char* hdst = (char*)h_s;
#pragma unroll
        for (int i = 0; i < 8; i++) {
            int off = (tid + i * 128) * 16;
            cp16cg(hdst + off, hsrc + off);
        }
        CP_COMMIT();
        // prefetch xe(t+1)
        if (t + 1 < NT)
            cp16cg(&xe_s[((t + 1) & 1) * 512 + bl * 64 + cq * 4],
                   &g_xe[br][t + 1][b][col]);
        CP_COMMIT();
        CP_WAIT1();        // h(t) + xe(t) done; xe(t+1) may stay in flight
        __syncthreads();

        float4 xe4 = *(const float4*)&xe_s[(t & 1) * 512 + bl * 64 + cq * 4];
        u64 acc01 = pack2(xe4.x, xe4.y);
        u64 acc23 = pack2(xe4.z, xe4.w);

        const float4* hrow = (const float4*)&h_s[bl * NH];
#pragma unroll 4
        for (int k4 = 0; k4 < NH / 4; k4++) {
            float4 h4 = hrow[k4];
            u64 hd; ulonglong2 w;
            hd = dup2(h4.x); w = wrow[(4 * k4 + 0) * 16 + cq]; fma2(acc01, hd, w.x); fma2(acc23, hd, w.y);
            hd = dup2(h4.y); w = wrow[(4 * k4 + 1) * 16 + cq]; fma2(acc01, hd, w.x); fma2(acc23, hd, w.y);
            hd = dup2(h4.z); w = wrow[(4 * k4 + 2) * 16 + cq]; fma2(acc01, hd, w.x); fma2(acc23, hd, w.y);
            hd = dup2(h4.w); w = wrow[(4 * k4 + 3) * 16 + cq]; fma2(acc01, hd, w.x); fma2(acc23, hd, w.y);
        }

        unpack2(acc01, v0, v1);
        unpack2(acc23, v2, v3);
        if (br) {
            v0 = fmaxf(v0, 0.f); v1 = fmaxf(v1, 0.f);
            v2 = fmaxf(v2, 0.f); v3 = fmaxf(v3, 0.f);
        } else {
            v0 = tanh_fast(v0); v1 = tanh_fast(v1);
            v2 = tanh_fast(v2); v3 = tanh_fast(v3);
        }
        float4 o = make_float4(v0, v1, v2, v3);
        __stcg((float4*)&g_h[br][(t + 1) & 1][b][col], o);

        CLUSTER_BAR();     // release writes / acquire peers' writes, row-wide
    }

    // out[b] += sum over owned cols of h_T[b,col] * fc_w[br*H + col]
    const float4 f4 = *(const float4*)&fcw[br * NH + col];
    float p = v0 * f4.x + v1 * f4.y + v2 * f4.z + v3 * f4.w;
#pragma unroll
    for (int off = 8; off; off >>= 1)
        p += __shfl_down_sync(0xffffffffu, p, off, 16);
    if (cq == 0) atomicAdd(&out[b], p);
}

// ---------------- launch ----------------
extern "C" void kernel_launch(void* const* d_in, const int* in_sizes, int n_in,
                              void* d_out, int out_size) {
    const int*   x    = (const int*)  d_in[0];
    const float* emb  = (const float*)d_in[1];
    const float* Wx0  = (const float*)d_in[2];
    const float* Wh0  = (const float*)d_in[3];
    const float* b0   = (const float*)d_in[4];
    const float* Wx1  = (const float*)d_in[5];
    const float* Wh1  = (const float*)d_in[6];
    const float* b1   = (const float*)d_in[7];
    const float* fcw  = (const float*)d_in[8];
    const float* fcb  = (const float*)d_in[9];
    float* out = (float*)d_out;

    const int rec_smem_bytes = (NH * 64 + 8 * NH + 2 * 8 * 64) * (int)sizeof(float);
    cudaFuncSetAttribute(rec_kernel, cudaFuncAttributeMaxDynamicSharedMemorySize,
                         rec_smem_bytes);

    init_out_kernel<<<1, 64>>>(out, fcb);
    proj_kernel<<<dim3(8, 512, 2), 256>>>(x, emb, Wx0, b0, Wx1, b1);
    rec_kernel<<<128, 128, rec_smem_bytes>>>(Wh0, Wh1, fcw, out);
}